// round 1
// baseline (speedup 1.0000x reference)
#include <cuda_runtime.h>
#include <cuda_bf16.h>
#include <math.h>

// Problem constants
#define BN_   2
#define SQ    2048
#define DM    1024
#define NHEAD 16
#define HD    64
#define NS    (BN_*SQ)        // 4096 rows
#define QKVD  (3*DM)          // 3072

// Scratch (device globals: alloc-free rule)
__device__ float g_qkv[(size_t)NS * QKVD];   // ~50 MB
__device__ float g_vals[(size_t)NS * DM];    // ~16 MB

// ---------------------------------------------------------------------------
// GEMM: C[M,N] = A[M,K] * B[N,K]^T   (torch Linear layout, no bias)
// 128x128 block, BK=16, 256 threads, 8x8 microtile.
// ---------------------------------------------------------------------------
__global__ void __launch_bounds__(256) gemm_tn(const float* __restrict__ A,
                                               const float* __restrict__ B,
                                               float* __restrict__ C,
                                               int M, int N, int K) {
    __shared__ float As[16][128];
    __shared__ float Bs[16][128];

    const int tid = threadIdx.x;
    const int tx  = tid & 15;
    const int ty  = tid >> 4;
    const int m0  = blockIdx.y * 128;
    const int n0  = blockIdx.x * 128;

    const int lrow = tid >> 2;        // 0..63
    const int lcol = (tid & 3) * 4;   // 0,4,8,12

    const float* Ap = A + (size_t)(m0 + lrow) * K + lcol;
    const float* Bp = B + (size_t)(n0 + lrow) * K + lcol;

    float acc[8][8];
#pragma unroll
    for (int i = 0; i < 8; i++)
#pragma unroll
        for (int j = 0; j < 8; j++) acc[i][j] = 0.f;

    for (int k0 = 0; k0 < K; k0 += 16) {
        float4 a0 = *(const float4*)(Ap + k0);
        float4 a1 = *(const float4*)(Ap + k0 + (size_t)64 * K);
        float4 b0 = *(const float4*)(Bp + k0);
        float4 b1 = *(const float4*)(Bp + k0 + (size_t)64 * K);
        __syncthreads();   // previous tile's compute done
        As[lcol+0][lrow]    = a0.x; As[lcol+1][lrow]    = a0.y;
        As[lcol+2][lrow]    = a0.z; As[lcol+3][lrow]    = a0.w;
        As[lcol+0][lrow+64] = a1.x; As[lcol+1][lrow+64] = a1.y;
        As[lcol+2][lrow+64] = a1.z; As[lcol+3][lrow+64] = a1.w;
        Bs[lcol+0][lrow]    = b0.x; Bs[lcol+1][lrow]    = b0.y;
        Bs[lcol+2][lrow]    = b0.z; Bs[lcol+3][lrow]    = b0.w;
        Bs[lcol+0][lrow+64] = b1.x; Bs[lcol+1][lrow+64] = b1.y;
        Bs[lcol+2][lrow+64] = b1.z; Bs[lcol+3][lrow+64] = b1.w;
        __syncthreads();

#pragma unroll
        for (int kk = 0; kk < 16; kk++) {
            float4 av0 = *(const float4*)&As[kk][ty * 8];
            float4 av1 = *(const float4*)&As[kk][ty * 8 + 4];
            float4 bv0 = *(const float4*)&Bs[kk][tx * 8];
            float4 bv1 = *(const float4*)&Bs[kk][tx * 8 + 4];
            float a[8] = {av0.x, av0.y, av0.z, av0.w, av1.x, av1.y, av1.z, av1.w};
            float b[8] = {bv0.x, bv0.y, bv0.z, bv0.w, bv1.x, bv1.y, bv1.z, bv1.w};
#pragma unroll
            for (int i = 0; i < 8; i++)
#pragma unroll
                for (int j = 0; j < 8; j++)
                    acc[i][j] = fmaf(a[i], b[j], acc[i][j]);
        }
    }

#pragma unroll
    for (int i = 0; i < 8; i++) {
        float* crow = C + (size_t)(m0 + ty * 8 + i) * N + n0 + tx * 8;
        ((float4*)crow)[0] = make_float4(acc[i][0], acc[i][1], acc[i][2], acc[i][3]);
        ((float4*)crow)[1] = make_float4(acc[i][4], acc[i][5], acc[i][6], acc[i][7]);
    }
}

// ---------------------------------------------------------------------------
// Flash attention (fp32). One CTA = one (head, 64-row q-block).
// S-tile 64x64, 4x4 microtile with strided lane map:
//   row_i = ty + 16*i, col_j = tx + 16*j  -> all smem reads conflict-free.
// qkv layout: g_qkv[(n*SQ+s)*3072 + h*192 + {0|64|128} + d]
// vals layout: g_vals[(n*SQ+s)*1024 + h*64 + d]
// ---------------------------------------------------------------------------
#define PADW 65
#define ATTN_SMEM (4 * 64 * PADW * (int)sizeof(float))   // 66560 B

__global__ void __launch_bounds__(256) attn_kernel(const float* __restrict__ qkv,
                                                   float* __restrict__ vals) {
    extern __shared__ float sm[];
    float* Qs = sm;                 // [64][PADW]
    float* Ks = sm + 64 * PADW;     // [64][PADW]
    float* Vs = sm + 2 * 64 * PADW; // [64][PADW]
    float* Ps = sm + 3 * 64 * PADW; // [64][PADW]

    const int tid = threadIdx.x;
    const int tx  = tid & 15;
    const int ty  = tid >> 4;
    const int nh  = blockIdx.y;
    const int n   = nh >> 4;
    const int h   = nh & 15;
    const int q0  = blockIdx.x * 64;

    const float* base = qkv + (size_t)n * SQ * QKVD + h * (3 * HD);

    // Load + scale Q tile (scale = 1/sqrt(64) = 0.125)
    for (int i = tid; i < 64 * 64; i += 256) {
        int r = i >> 6, d = i & 63;
        Qs[r * PADW + d] = base[(size_t)(q0 + r) * QKVD + d] * 0.125f;
    }

    float m_r[4], l_r[4], o_acc[4][4];
#pragma unroll
    for (int i = 0; i < 4; i++) {
        m_r[i] = -INFINITY; l_r[i] = 0.f;
#pragma unroll
        for (int j = 0; j < 4; j++) o_acc[i][j] = 0.f;
    }

    for (int kb = 0; kb < SQ / 64; kb++) {
        const int kbase = kb * 64;
        __syncthreads();   // Qs ready (iter 0) / previous PV done
        for (int i = tid; i < 64 * 64; i += 256) {
            int r = i >> 6, d = i & 63;
            const float* rp = base + (size_t)(kbase + r) * QKVD;
            Ks[r * PADW + d] = rp[HD + d];
            Vs[r * PADW + d] = rp[2 * HD + d];
        }
        __syncthreads();

        // S = Q * K^T
        float s[4][4];
#pragma unroll
        for (int i = 0; i < 4; i++)
#pragma unroll
            for (int j = 0; j < 4; j++) s[i][j] = 0.f;

#pragma unroll 8
        for (int k = 0; k < 64; k++) {
            float a[4], b[4];
#pragma unroll
            for (int i = 0; i < 4; i++) a[i] = Qs[(ty + 16 * i) * PADW + k];
#pragma unroll
            for (int j = 0; j < 4; j++) b[j] = Ks[(tx + 16 * j) * PADW + k];
#pragma unroll
            for (int i = 0; i < 4; i++)
#pragma unroll
                for (int j = 0; j < 4; j++)
                    s[i][j] = fmaf(a[i], b[j], s[i][j]);
        }

        // Online softmax (per-row stats replicated across the 16 tx lanes)
#pragma unroll
        for (int i = 0; i < 4; i++) {
            float mx = fmaxf(fmaxf(s[i][0], s[i][1]), fmaxf(s[i][2], s[i][3]));
#pragma unroll
            for (int off = 8; off > 0; off >>= 1)
                mx = fmaxf(mx, __shfl_xor_sync(0xffffffffu, mx, off));
            float mo   = m_r[i];
            float mn   = fmaxf(mo, mx);
            float corr = __expf(mo - mn);          // -inf start -> 0
            float rs = 0.f;
#pragma unroll
            for (int j = 0; j < 4; j++) {
                float p = __expf(s[i][j] - mn);
                Ps[(ty + 16 * i) * PADW + (tx + 16 * j)] = p;
                rs += p;
            }
#pragma unroll
            for (int off = 8; off > 0; off >>= 1)
                rs += __shfl_xor_sync(0xffffffffu, rs, off);
            l_r[i] = l_r[i] * corr + rs;
            m_r[i] = mn;
#pragma unroll
            for (int j = 0; j < 4; j++) o_acc[i][j] *= corr;
        }
        __syncthreads();   // Ps visible to all

        // O += P * V
#pragma unroll 8
        for (int k = 0; k < 64; k++) {
            float a[4], b[4];
#pragma unroll
            for (int i = 0; i < 4; i++) a[i] = Ps[(ty + 16 * i) * PADW + k];
#pragma unroll
            for (int j = 0; j < 4; j++) b[j] = Vs[k * PADW + tx + 16 * j];
#pragma unroll
            for (int i = 0; i < 4; i++)
#pragma unroll
                for (int j = 0; j < 4; j++)
                    o_acc[i][j] = fmaf(a[i], b[j], o_acc[i][j]);
        }
    }

    // Normalize and write to values buffer (n, s, h*64 + d)
    float* obase = vals + (size_t)(n * SQ + q0) * DM + h * HD;
#pragma unroll
    for (int i = 0; i < 4; i++) {
        float inv = 1.0f / l_r[i];
#pragma unroll
        for (int j = 0; j < 4; j++)
            obase[(size_t)(ty + 16 * i) * DM + tx + 16 * j] = o_acc[i][j] * inv;
    }
}

// ---------------------------------------------------------------------------
extern "C" void kernel_launch(void* const* d_in, const int* in_sizes, int n_in,
                              void* d_out, int out_size) {
    const float* x     = (const float*)d_in[0];   // (2,2048,1024)
    const float* qkv_w = (const float*)d_in[1];   // (3072,1024)
    const float* o_w   = (const float*)d_in[2];   // (1024,1024)
    float* out = (float*)d_out;                   // (2,2048,1024)

    float *qkv_p = nullptr, *vals_p = nullptr;
    cudaGetSymbolAddress((void**)&qkv_p,  g_qkv);
    cudaGetSymbolAddress((void**)&vals_p, g_vals);

    cudaFuncSetAttribute(attn_kernel,
                         cudaFuncAttributeMaxDynamicSharedMemorySize, ATTN_SMEM);

    // 1) QKV projection: [4096,3072] = x[4096,1024] @ qkv_w^T
    gemm_tn<<<dim3(QKVD / 128, NS / 128), 256>>>(x, qkv_w, qkv_p, NS, QKVD, DM);

    // 2) Attention: 32 q-blocks x 32 (n,h) pairs
    attn_kernel<<<dim3(SQ / 64, BN_ * NHEAD), 256, ATTN_SMEM>>>(qkv_p, vals_p);

    // 3) Output projection: out[4096,1024] = vals @ o_w^T
    gemm_tn<<<dim3(DM / 128, NS / 128), 256>>>(vals_p, o_w, out, NS, DM, DM);
}

// round 2
// speedup vs baseline: 3.2419x; 3.2419x over previous
#include <cuda_runtime.h>
#include <cuda_bf16.h>
#include <math.h>

// Problem constants
#define BN_   2
#define SQ    2048
#define DM    1024
#define NHEAD 16
#define HD    64
#define NS    (BN_*SQ)        // 4096 rows
#define QKVD  (3*DM)          // 3072

// Scratch (device globals: alloc-free rule)
__device__ float g_qkv[(size_t)NS * QKVD];   // ~50 MB
__device__ float g_vals[(size_t)NS * DM];    // ~16 MB

// ---------------------------------------------------------------------------
// tf32 helpers
// ---------------------------------------------------------------------------
__device__ __forceinline__ float cvt_tf32(float x) {
    unsigned u;
    asm("cvt.rna.tf32.f32 %0, %1;" : "=r"(u) : "f"(x));
    return __uint_as_float(u);
}

__device__ __forceinline__ void mma8(float4& d,
                                     unsigned a0, unsigned a1, unsigned a2, unsigned a3,
                                     unsigned b0, unsigned b1) {
    asm("mma.sync.aligned.m16n8k8.row.col.f32.tf32.tf32.f32 "
        "{%0,%1,%2,%3},{%4,%5,%6,%7},{%8,%9},{%0,%1,%2,%3};"
        : "+f"(d.x), "+f"(d.y), "+f"(d.z), "+f"(d.w)
        : "r"(a0), "r"(a1), "r"(a2), "r"(a3), "r"(b0), "r"(b1));
}

__device__ __forceinline__ float4 cvt4(float4 v) {
    return make_float4(cvt_tf32(v.x), cvt_tf32(v.y), cvt_tf32(v.z), cvt_tf32(v.w));
}

// ---------------------------------------------------------------------------
// GEMM: C[M,N] = A[M,K] * B[N,K]^T  via tf32 mma.sync
// block 256 thr (8 warps), tile 128x128, BK=32, warp tile 64x32.
// smem [row][36]: pad 36 => frag reads are lane-distinct mod 32 (conflict-free).
// ---------------------------------------------------------------------------
#define GPAD 36
__global__ void __launch_bounds__(256) gemm_mma(const float* __restrict__ A,
                                                const float* __restrict__ B,
                                                float* __restrict__ C,
                                                int M, int N, int K) {
    __shared__ float As[128][GPAD];
    __shared__ float Bs[128][GPAD];

    const int tid  = threadIdx.x;
    const int lane = tid & 31;
    const int warp = tid >> 5;
    const int g    = lane >> 2;       // 0..7
    const int q    = lane & 3;        // 0..3
    const int wm   = warp >> 2;       // 0..1
    const int wn   = warp & 3;        // 0..3
    const int m0   = blockIdx.y * 128;
    const int n0   = blockIdx.x * 128;

    const int lrow = tid >> 3;        // 0..31 (per pass)
    const int lk   = (tid & 7) * 4;   // 0..28

    float4 acc[4][4];
#pragma unroll
    for (int i = 0; i < 4; i++)
#pragma unroll
        for (int j = 0; j < 4; j++) acc[i][j] = make_float4(0.f, 0.f, 0.f, 0.f);

    for (int k0 = 0; k0 < K; k0 += 32) {
        __syncthreads();
#pragma unroll
        for (int p = 0; p < 4; p++) {
            int row = lrow + 32 * p;
            float4 av = *(const float4*)(A + (size_t)(m0 + row) * K + k0 + lk);
            float4 bv = *(const float4*)(B + (size_t)(n0 + row) * K + k0 + lk);
            *(float4*)&As[row][lk] = cvt4(av);
            *(float4*)&Bs[row][lk] = cvt4(bv);
        }
        __syncthreads();

#pragma unroll
        for (int c = 0; c < 4; c++) {
            unsigned af[4][4];
#pragma unroll
            for (int i = 0; i < 4; i++) {
                int r = wm * 64 + 16 * i + g;
                af[i][0] = __float_as_uint(As[r][8 * c + q]);
                af[i][1] = __float_as_uint(As[r + 8][8 * c + q]);
                af[i][2] = __float_as_uint(As[r][8 * c + 4 + q]);
                af[i][3] = __float_as_uint(As[r + 8][8 * c + 4 + q]);
            }
#pragma unroll
            for (int j = 0; j < 4; j++) {
                int n = wn * 32 + 8 * j + g;
                unsigned b0 = __float_as_uint(Bs[n][8 * c + q]);
                unsigned b1 = __float_as_uint(Bs[n][8 * c + 4 + q]);
#pragma unroll
                for (int i = 0; i < 4; i++)
                    mma8(acc[i][j], af[i][0], af[i][1], af[i][2], af[i][3], b0, b1);
            }
        }
    }

#pragma unroll
    for (int i = 0; i < 4; i++) {
#pragma unroll
        for (int j = 0; j < 4; j++) {
            int row = m0 + wm * 64 + 16 * i + g;
            int col = n0 + wn * 32 + 8 * j + 2 * q;
            *(float2*)&C[(size_t)row * N + col]       = make_float2(acc[i][j].x, acc[i][j].y);
            *(float2*)&C[(size_t)(row + 8) * N + col] = make_float2(acc[i][j].z, acc[i][j].w);
        }
    }
}

// ---------------------------------------------------------------------------
// Flash attention via tf32 mma.sync.
// CTA: 128 thr (4 warps), q-tile 64, k-tile 64, hd 64. Warp owns 16 q-rows.
// Q fragments held in registers for the whole kernel.
// smem pad 68 (=4 mod 32) => all fragment loads conflict-free.
// ---------------------------------------------------------------------------
#define AT_PAD 68
#define ATTN_SMEM (3 * 64 * AT_PAD * (int)sizeof(float))   // 52224 B

__global__ void __launch_bounds__(128) attn_mma(const float* __restrict__ qkv,
                                                float* __restrict__ vals) {
    extern __shared__ float sm[];
    float* Ks = sm;
    float* Vs = sm + 64 * AT_PAD;
    float* Ps = sm + 2 * 64 * AT_PAD;

    const int tid  = threadIdx.x;
    const int lane = tid & 31;
    const int warp = tid >> 5;
    const int g    = lane >> 2;
    const int q    = lane & 3;
    const int row0 = warp * 16 + g;      // thread's first local q-row (second = +8)

    const int nh = blockIdx.y;
    const int n  = nh >> 4;
    const int h  = nh & 15;
    const int q0 = blockIdx.x * 64;

    const float* base = qkv + (size_t)n * SQ * QKVD + h * (3 * HD);

    // --- Stage Q tile (scaled, tf32-rounded) into Ks, then lift frags to regs
    for (int i = tid; i < 64 * 16; i += 128) {
        int r = i >> 4, d4 = (i & 15) * 4;
        float4 v = *(const float4*)(base + (size_t)(q0 + r) * QKVD + d4);
        v.x *= 0.125f; v.y *= 0.125f; v.z *= 0.125f; v.w *= 0.125f;
        *(float4*)&Ks[r * AT_PAD + d4] = cvt4(v);
    }
    __syncthreads();

    unsigned qf[8][4];
#pragma unroll
    for (int c = 0; c < 8; c++) {
        qf[c][0] = __float_as_uint(Ks[row0 * AT_PAD + 8 * c + q]);
        qf[c][1] = __float_as_uint(Ks[(row0 + 8) * AT_PAD + 8 * c + q]);
        qf[c][2] = __float_as_uint(Ks[row0 * AT_PAD + 8 * c + 4 + q]);
        qf[c][3] = __float_as_uint(Ks[(row0 + 8) * AT_PAD + 8 * c + 4 + q]);
    }

    float m0r = -INFINITY, m1r = -INFINITY, l0r = 0.f, l1r = 0.f;
    float4 oacc[8];
#pragma unroll
    for (int t = 0; t < 8; t++) oacc[t] = make_float4(0.f, 0.f, 0.f, 0.f);

    for (int kb = 0; kb < SQ / 64; kb++) {
        __syncthreads();   // prev compute done / Q frags lifted
        for (int i = tid; i < 64 * 16; i += 128) {
            int r = i >> 4, d4 = (i & 15) * 4;
            const float* rp = base + (size_t)(kb * 64 + r) * QKVD;
            *(float4*)&Ks[r * AT_PAD + d4] = cvt4(*(const float4*)(rp + HD + d4));
            *(float4*)&Vs[r * AT_PAD + d4] = cvt4(*(const float4*)(rp + 2 * HD + d4));
        }
        __syncthreads();

        // ---- S = Q K^T  (16 rows x 64 cols per warp)
        float4 sc[8];
#pragma unroll
        for (int j = 0; j < 8; j++) sc[j] = make_float4(0.f, 0.f, 0.f, 0.f);
#pragma unroll
        for (int c = 0; c < 8; c++) {
#pragma unroll
            for (int j = 0; j < 8; j++) {
                unsigned b0 = __float_as_uint(Ks[(8 * j + g) * AT_PAD + 8 * c + q]);
                unsigned b1 = __float_as_uint(Ks[(8 * j + g) * AT_PAD + 8 * c + 4 + q]);
                mma8(sc[j], qf[c][0], qf[c][1], qf[c][2], qf[c][3], b0, b1);
            }
        }

        // ---- online softmax (rows row0, row0+8)
        float mx0 = -INFINITY, mx1 = -INFINITY;
#pragma unroll
        for (int j = 0; j < 8; j++) {
            mx0 = fmaxf(mx0, fmaxf(sc[j].x, sc[j].y));
            mx1 = fmaxf(mx1, fmaxf(sc[j].z, sc[j].w));
        }
#pragma unroll
        for (int off = 1; off <= 2; off <<= 1) {
            mx0 = fmaxf(mx0, __shfl_xor_sync(0xffffffffu, mx0, off));
            mx1 = fmaxf(mx1, __shfl_xor_sync(0xffffffffu, mx1, off));
        }
        float mn0 = fmaxf(m0r, mx0), mn1 = fmaxf(m1r, mx1);
        float corr0 = __expf(m0r - mn0), corr1 = __expf(m1r - mn1);

        float rs0 = 0.f, rs1 = 0.f;
#pragma unroll
        for (int j = 0; j < 8; j++) {
            float p0 = __expf(sc[j].x - mn0);
            float p1 = __expf(sc[j].y - mn0);
            float p2 = __expf(sc[j].z - mn1);
            float p3 = __expf(sc[j].w - mn1);
            rs0 += p0 + p1; rs1 += p2 + p3;
            int col = 8 * j + 2 * q;
            *(float2*)&Ps[row0 * AT_PAD + col]       = make_float2(cvt_tf32(p0), cvt_tf32(p1));
            *(float2*)&Ps[(row0 + 8) * AT_PAD + col] = make_float2(cvt_tf32(p2), cvt_tf32(p3));
        }
#pragma unroll
        for (int off = 1; off <= 2; off <<= 1) {
            rs0 += __shfl_xor_sync(0xffffffffu, rs0, off);
            rs1 += __shfl_xor_sync(0xffffffffu, rs1, off);
        }
        l0r = l0r * corr0 + rs0;  m0r = mn0;
        l1r = l1r * corr1 + rs1;  m1r = mn1;
#pragma unroll
        for (int t = 0; t < 8; t++) {
            oacc[t].x *= corr0; oacc[t].y *= corr0;
            oacc[t].z *= corr1; oacc[t].w *= corr1;
        }
        __syncwarp();   // P strip (warp-private rows) visible to whole warp

        // ---- O += P V  (16 rows x 64 d per warp)
#pragma unroll
        for (int c = 0; c < 8; c++) {
            unsigned a0 = __float_as_uint(Ps[row0 * AT_PAD + 8 * c + q]);
            unsigned a1 = __float_as_uint(Ps[(row0 + 8) * AT_PAD + 8 * c + q]);
            unsigned a2 = __float_as_uint(Ps[row0 * AT_PAD + 8 * c + 4 + q]);
            unsigned a3 = __float_as_uint(Ps[(row0 + 8) * AT_PAD + 8 * c + 4 + q]);
#pragma unroll
            for (int t = 0; t < 8; t++) {
                unsigned b0 = __float_as_uint(Vs[(8 * c + q) * AT_PAD + 8 * t + g]);
                unsigned b1 = __float_as_uint(Vs[(8 * c + 4 + q) * AT_PAD + 8 * t + g]);
                mma8(oacc[t], a0, a1, a2, a3, b0, b1);
            }
        }
    }

    // ---- normalize + write
    float inv0 = 1.0f / l0r, inv1 = 1.0f / l1r;
    float* obase = vals + (size_t)(n * SQ + q0) * DM + h * HD;
#pragma unroll
    for (int t = 0; t < 8; t++) {
        int col = 8 * t + 2 * q;
        *(float2*)&obase[(size_t)row0 * DM + col] =
            make_float2(oacc[t].x * inv0, oacc[t].y * inv0);
        *(float2*)&obase[(size_t)(row0 + 8) * DM + col] =
            make_float2(oacc[t].z * inv1, oacc[t].w * inv1);
    }
}

// ---------------------------------------------------------------------------
extern "C" void kernel_launch(void* const* d_in, const int* in_sizes, int n_in,
                              void* d_out, int out_size) {
    const float* x     = (const float*)d_in[0];   // (2,2048,1024)
    const float* qkv_w = (const float*)d_in[1];   // (3072,1024)
    const float* o_w   = (const float*)d_in[2];   // (1024,1024)
    float* out = (float*)d_out;                   // (2,2048,1024)

    float *qkv_p = nullptr, *vals_p = nullptr;
    cudaGetSymbolAddress((void**)&qkv_p,  g_qkv);
    cudaGetSymbolAddress((void**)&vals_p, g_vals);

    cudaFuncSetAttribute(attn_mma,
                         cudaFuncAttributeMaxDynamicSharedMemorySize, ATTN_SMEM);

    // 1) QKV projection: [4096,3072] = x @ qkv_w^T
    gemm_mma<<<dim3(QKVD / 128, NS / 128), 256>>>(x, qkv_w, qkv_p, NS, QKVD, DM);

    // 2) Attention
    attn_mma<<<dim3(SQ / 64, BN_ * NHEAD), 128, ATTN_SMEM>>>(qkv_p, vals_p);

    // 3) Output projection: out = vals @ o_w^T
    gemm_mma<<<dim3(DM / 128, NS / 128), 256>>>(vals_p, o_w, out, NS, DM, DM);
}

// round 3
// speedup vs baseline: 3.4364x; 1.0600x over previous
#include <cuda_runtime.h>
#include <math.h>

// Problem constants
#define BN_   2
#define SQ    2048
#define DM    1024
#define NHEAD 16
#define HD    64
#define NS    (BN_*SQ)        // 4096
#define QKVD  (3*DM)          // 3072

__device__ float g_qkv[(size_t)NS * QKVD];
__device__ float g_vals[(size_t)NS * DM];

__device__ __forceinline__ float cvt_tf32(float x) {
    unsigned u; asm("cvt.rna.tf32.f32 %0, %1;" : "=r"(u) : "f"(x));
    return __uint_as_float(u);
}
__device__ __forceinline__ float4 cvt4(float4 v) {
    return make_float4(cvt_tf32(v.x), cvt_tf32(v.y), cvt_tf32(v.z), cvt_tf32(v.w));
}
__device__ __forceinline__ void mma8(float4& d, float4 a, float b0, float b1) {
    asm("mma.sync.aligned.m16n8k8.row.col.f32.tf32.tf32.f32 "
        "{%0,%1,%2,%3},{%4,%5,%6,%7},{%8,%9},{%0,%1,%2,%3};"
        : "+f"(d.x), "+f"(d.y), "+f"(d.z), "+f"(d.w)
        : "r"(__float_as_uint(a.x)), "r"(__float_as_uint(a.y)),
          "r"(__float_as_uint(a.z)), "r"(__float_as_uint(a.w)),
          "r"(__float_as_uint(b0)),  "r"(__float_as_uint(b1)));
}

// ---------------------------------------------------------------------------
// GEMM: C[M,N] = A[M,K]*B[N,K]^T, 128x128x32 tiles, 8 warps (warp 64x32),
// quad-packed smem (LDS.128 frags), double-buffered, register prefetch.
// ---------------------------------------------------------------------------
// A quad store: value (row, col) in 128x32 tile:
//   c=col>>3, kq=col&3, chalf=(col>>2)&1, g=row&7, R=row>>4, e=((row>>3)&1)+2*chalf
//   float addr = ((R*4+c)*8+g)*16 + ((kq^c)*4) + e
__device__ __forceinline__ void stA_quad(float* buf, int row, int cst, int chalf, float4 v) {
    int gg = row & 7, R = row >> 4;
    int e  = ((row >> 3) & 1) + 2 * chalf;
    float* qb = buf + ((((R * 4 + cst) * 8 + gg) << 4) + e);
    int cx = cst & 3;
    qb[(0 ^ cx) << 2] = cvt_tf32(v.x);
    qb[(1 ^ cx) << 2] = cvt_tf32(v.y);
    qb[(2 ^ cx) << 2] = cvt_tf32(v.z);
    qb[(3 ^ cx) << 2] = cvt_tf32(v.w);
}
// B quad: value (n, col): Ng=n>>5, jj=(n>>3)&1, g=n&7, e=2*((n>>4)&1)+chalf
__device__ __forceinline__ void stB_quad(float* buf, int n, int cst, int chalf, float4 v) {
    int gg = n & 7, Ng = n >> 5, jj = (n >> 3) & 1;
    int e  = 2 * ((n >> 4) & 1) + chalf;
    float* qb = buf + (((((Ng * 2 + jj) * 4 + cst) * 8 + gg) << 4) + e);
    int cx = cst & 3;
    qb[(0 ^ cx) << 2] = cvt_tf32(v.x);
    qb[(1 ^ cx) << 2] = cvt_tf32(v.y);
    qb[(2 ^ cx) << 2] = cvt_tf32(v.z);
    qb[(3 ^ cx) << 2] = cvt_tf32(v.w);
}

#define GEMM_SMEM (2 * 8192 * (int)sizeof(float))  // 65536 B

__global__ void __launch_bounds__(256, 2) gemm_mma(const float* __restrict__ A,
                                                   const float* __restrict__ B,
                                                   float* __restrict__ C,
                                                   int M, int N, int K) {
    extern __shared__ float gsm[];   // buf0: A[0,4096) B[4096,8192); buf1: +8192

    const int tid  = threadIdx.x;
    const int lane = tid & 31;
    const int warp = tid >> 5;
    const int g    = lane >> 2;
    const int q    = lane & 3;
    const int wm   = warp >> 2;
    const int wn   = warp & 3;
    const int m0   = blockIdx.y * 128;
    const int n0   = blockIdx.x * 128;

    const int lrow  = tid >> 3;          // 0..31
    const int lk4   = (tid & 7) * 4;     // 0..28
    const int cst   = lk4 >> 3;          // 0..3
    const int chalf = (lk4 >> 2) & 1;

    const float* Ap = A + (size_t)(m0 + lrow) * K + lk4;
    const float* Bp = B + (size_t)(n0 + lrow) * K + lk4;

    float4 acc[4][4];
#pragma unroll
    for (int i = 0; i < 4; i++)
#pragma unroll
        for (int j = 0; j < 4; j++) acc[i][j] = make_float4(0.f, 0.f, 0.f, 0.f);

    float4 pa[4], pb[4];
    // prologue: tile 0
#pragma unroll
    for (int p = 0; p < 4; p++) {
        pa[p] = *(const float4*)(Ap + (size_t)(32 * p) * K);
        pb[p] = *(const float4*)(Bp + (size_t)(32 * p) * K);
    }
#pragma unroll
    for (int p = 0; p < 4; p++) {
        stA_quad(gsm,        lrow + 32 * p, cst, chalf, pa[p]);
        stB_quad(gsm + 4096, lrow + 32 * p, cst, chalf, pb[p]);
    }
    __syncthreads();

    const int T = K >> 5;
    for (int t = 0; t < T; t++) {
        float* cb = gsm + (t & 1) * 8192;

        if (t + 1 < T) {
            int k0 = (t + 1) << 5;
#pragma unroll
            for (int p = 0; p < 4; p++) {
                pa[p] = *(const float4*)(Ap + (size_t)(32 * p) * K + k0);
                pb[p] = *(const float4*)(Bp + (size_t)(32 * p) * K + k0);
            }
        }

        // compute current tile
#pragma unroll
        for (int c = 0; c < 4; c++) {
            float4 aq[4], bq[2];
#pragma unroll
            for (int i = 0; i < 4; i++)
                aq[i] = *(float4*)(cb + (((((wm * 4 + i) * 4 + c) * 8 + g) << 4) + ((q ^ c) << 2)));
#pragma unroll
            for (int jj = 0; jj < 2; jj++)
                bq[jj] = *(float4*)(cb + 4096 + (((((wn * 2 + jj) * 4 + c) * 8 + g) << 4) + ((q ^ c) << 2)));
#pragma unroll
            for (int i = 0; i < 4; i++) {
                mma8(acc[i][0], aq[i], bq[0].x, bq[0].y);
                mma8(acc[i][2], aq[i], bq[0].z, bq[0].w);
                mma8(acc[i][1], aq[i], bq[1].x, bq[1].y);
                mma8(acc[i][3], aq[i], bq[1].z, bq[1].w);
            }
        }

        if (t + 1 < T) {
            float* nb = gsm + ((t + 1) & 1) * 8192;
#pragma unroll
            for (int p = 0; p < 4; p++) {
                stA_quad(nb,        lrow + 32 * p, cst, chalf, pa[p]);
                stB_quad(nb + 4096, lrow + 32 * p, cst, chalf, pb[p]);
            }
        }
        __syncthreads();
    }

#pragma unroll
    for (int i = 0; i < 4; i++) {
#pragma unroll
        for (int j = 0; j < 4; j++) {
            int row = m0 + wm * 64 + 16 * i + g;
            int col = n0 + wn * 32 + 8 * j + 2 * q;
            *(float2*)&C[(size_t)row * N + col]       = make_float2(acc[i][j].x, acc[i][j].y);
            *(float2*)&C[(size_t)(row + 8) * N + col] = make_float2(acc[i][j].z, acc[i][j].w);
        }
    }
}

// ---------------------------------------------------------------------------
// Flash attention: 128 thr (4 warps), 64q x 64k tiles.
// K quad-packed (S-phase LDS.128), P quad-packed (PV A-side LDS.128),
// V padded [k][72] (conflict-free scalar). Q frags in registers.
// smem floats: KQ[0,4096) VS[4096,8704) PS[8704,12800)  -> 51200 B
// ---------------------------------------------------------------------------
#define ATTN_SMEM (12800 * (int)sizeof(float))

__global__ void __launch_bounds__(128) attn_mma(const float* __restrict__ qkv,
                                                float* __restrict__ vals) {
    extern __shared__ float sm[];
    float* KQ = sm;
    float* VS = sm + 4096;
    float* PS = sm + 8704;

    const int tid  = threadIdx.x;
    const int lane = tid & 31;
    const int warp = tid >> 5;
    const int g    = lane >> 2;
    const int q    = lane & 3;
    const int row0 = warp * 16 + g;

    const int nh = blockIdx.y;
    const int n  = nh >> 4;
    const int h  = nh & 15;
    const int q0 = blockIdx.x * 64;

    const float* base = qkv + (size_t)n * SQ * QKVD + h * (3 * HD);

    // stage Q (scaled) into VS, lift fragments to registers
#pragma unroll
    for (int p = 0; p < 8; p++) {
        int idx = tid + 128 * p;
        int r = idx >> 4, d4 = (idx & 15) * 4;
        float4 v = *(const float4*)(base + (size_t)(q0 + r) * QKVD + d4);
        v.x *= 0.125f; v.y *= 0.125f; v.z *= 0.125f; v.w *= 0.125f;
        *(float4*)&VS[r * 72 + d4] = cvt4(v);
    }
    __syncthreads();

    float4 qf[8];
#pragma unroll
    for (int c = 0; c < 8; c++)
        qf[c] = make_float4(VS[row0 * 72 + 8 * c + q],
                            VS[(row0 + 8) * 72 + 8 * c + q],
                            VS[row0 * 72 + 8 * c + 4 + q],
                            VS[(row0 + 8) * 72 + 8 * c + 4 + q]);

    float m0r = -INFINITY, m1r = -INFINITY, l0r = 0.f, l1r = 0.f;
    float4 oacc[8];
#pragma unroll
    for (int t = 0; t < 8; t++) oacc[t] = make_float4(0.f, 0.f, 0.f, 0.f);

    const int lrow  = tid >> 3;          // 0..15
    const int lk4   = (tid & 7) * 4;
    const int chalf = (lk4 >> 2) & 1;

    for (int kb = 0; kb < SQ / 64; kb++) {
        __syncthreads();   // protects VS/KQ/PS reuse (and first-iter q-frag lift)
        const float* kvb = base + (size_t)(kb * 64) * QKVD;

        // K -> quad-packed KQ
#pragma unroll
        for (int p = 0; p < 4; p++) {
#pragma unroll
            for (int kh = 0; kh < 2; kh++) {
                int nl  = lrow + 16 * p;
                int col = kh * 32 + lk4;
                float4 v = *(const float4*)(kvb + (size_t)nl * QKVD + HD + col);
                int cs = col >> 3, cx = cs & 3;
                int gg = nl & 7, Ng = nl >> 5, jj = (nl >> 3) & 1;
                int e  = 2 * ((nl >> 4) & 1) + chalf;
                float* qb = KQ + (((((Ng * 2 + jj) * 8 + cs) * 8 + gg) << 4) + e);
                qb[(0 ^ cx) << 2] = cvt_tf32(v.x);
                qb[(1 ^ cx) << 2] = cvt_tf32(v.y);
                qb[(2 ^ cx) << 2] = cvt_tf32(v.z);
                qb[(3 ^ cx) << 2] = cvt_tf32(v.w);
            }
        }
        // V -> VS [k][72]
#pragma unroll
        for (int p = 0; p < 8; p++) {
            int idx = tid + 128 * p;
            int r = idx >> 4, d4 = (idx & 15) * 4;
            *(float4*)&VS[r * 72 + d4] =
                cvt4(*(const float4*)(kvb + (size_t)r * QKVD + 2 * HD + d4));
        }
        __syncthreads();

        // ---- S = Q K^T
        float4 sc[8];
#pragma unroll
        for (int j = 0; j < 8; j++) sc[j] = make_float4(0.f, 0.f, 0.f, 0.f);
#pragma unroll
        for (int c = 0; c < 8; c++) {
#pragma unroll
            for (int Ng = 0; Ng < 2; Ng++) {
#pragma unroll
                for (int jj = 0; jj < 2; jj++) {
                    float4 b = *(float4*)(KQ + (((((Ng * 2 + jj) * 8 + c) * 8 + g) << 4)
                                                + ((q ^ (c & 3)) << 2)));
                    int jlo = 4 * Ng + jj;
                    mma8(sc[jlo],     qf[c], b.x, b.y);
                    mma8(sc[jlo + 2], qf[c], b.z, b.w);
                }
            }
        }

        // ---- online softmax
        float mx0 = -INFINITY, mx1 = -INFINITY;
#pragma unroll
        for (int j = 0; j < 8; j++) {
            mx0 = fmaxf(mx0, fmaxf(sc[j].x, sc[j].y));
            mx1 = fmaxf(mx1, fmaxf(sc[j].z, sc[j].w));
        }
#pragma unroll
        for (int off = 1; off <= 2; off <<= 1) {
            mx0 = fmaxf(mx0, __shfl_xor_sync(0xffffffffu, mx0, off));
            mx1 = fmaxf(mx1, __shfl_xor_sync(0xffffffffu, mx1, off));
        }
        float mn0 = fmaxf(m0r, mx0), mn1 = fmaxf(m1r, mx1);
        float corr0 = __expf(m0r - mn0), corr1 = __expf(m1r - mn1);

        const int kq0 = 2 * (q & 1), ch = q >> 1;
        float rs0 = 0.f, rs1 = 0.f;
#pragma unroll
        for (int j = 0; j < 8; j++) {
            float p0 = __expf(sc[j].x - mn0);   // (row0,   2q)
            float p1 = __expf(sc[j].y - mn0);   // (row0,   2q+1)
            float p2 = __expf(sc[j].z - mn1);   // (row0+8, 2q)
            float p3 = __expf(sc[j].w - mn1);   // (row0+8, 2q+1)
            rs0 += p0 + p1; rs1 += p2 + p3;
            float* bj = PS + (((warp * 8 + j) * 8 + g) << 4);
            *(float2*)&bj[(kq0 << 2)       + 2 * ch] = make_float2(cvt_tf32(p0), cvt_tf32(p2));
            *(float2*)&bj[((kq0 + 1) << 2) + 2 * ch] = make_float2(cvt_tf32(p1), cvt_tf32(p3));
        }
#pragma unroll
        for (int off = 1; off <= 2; off <<= 1) {
            rs0 += __shfl_xor_sync(0xffffffffu, rs0, off);
            rs1 += __shfl_xor_sync(0xffffffffu, rs1, off);
        }
        l0r = l0r * corr0 + rs0;  m0r = mn0;
        l1r = l1r * corr1 + rs1;  m1r = mn1;
#pragma unroll
        for (int t = 0; t < 8; t++) {
            oacc[t].x *= corr0; oacc[t].y *= corr0;
            oacc[t].z *= corr1; oacc[t].w *= corr1;
        }
        __syncwarp();   // warp-private P strip ready

        // ---- O += P V
#pragma unroll
        for (int c = 0; c < 8; c++) {
            float4 aq = *(float4*)(PS + ((((warp * 8 + c) * 8 + g) << 4) + (q << 2)));
#pragma unroll
            for (int t = 0; t < 8; t++) {
                float b0 = VS[(8 * c + q) * 72 + 8 * t + g];
                float b1 = VS[(8 * c + 4 + q) * 72 + 8 * t + g];
                mma8(oacc[t], aq, b0, b1);
            }
        }
    }

    float inv0 = 1.0f / l0r, inv1 = 1.0f / l1r;
    float* obase = vals + (size_t)(n * SQ + q0) * DM + h * HD;
#pragma unroll
    for (int t = 0; t < 8; t++) {
        int col = 8 * t + 2 * q;
        *(float2*)&obase[(size_t)row0 * DM + col] =
            make_float2(oacc[t].x * inv0, oacc[t].y * inv0);
        *(float2*)&obase[(size_t)(row0 + 8) * DM + col] =
            make_float2(oacc[t].z * inv1, oacc[t].w * inv1);
    }
}

// ---------------------------------------------------------------------------
extern "C" void kernel_launch(void* const* d_in, const int* in_sizes, int n_in,
                              void* d_out, int out_size) {
    const float* x     = (const float*)d_in[0];
    const float* qkv_w = (const float*)d_in[1];
    const float* o_w   = (const float*)d_in[2];
    float* out = (float*)d_out;

    float *qkv_p = nullptr, *vals_p = nullptr;
    cudaGetSymbolAddress((void**)&qkv_p,  g_qkv);
    cudaGetSymbolAddress((void**)&vals_p, g_vals);

    cudaFuncSetAttribute(gemm_mma, cudaFuncAttributeMaxDynamicSharedMemorySize, GEMM_SMEM);
    cudaFuncSetAttribute(attn_mma, cudaFuncAttributeMaxDynamicSharedMemorySize, ATTN_SMEM);

    gemm_mma<<<dim3(QKVD / 128, NS / 128), 256, GEMM_SMEM>>>(x, qkv_w, qkv_p, NS, QKVD, DM);
    attn_mma<<<dim3(SQ / 64, BN_ * NHEAD), 128, ATTN_SMEM>>>(qkv_p, vals_p);
    gemm_mma<<<dim3(DM / 128, NS / 128), 256, GEMM_SMEM>>>(vals_p, o_w, out, NS, DM, DM);
}

// round 5
// speedup vs baseline: 3.9404x; 1.1467x over previous
#include <cuda_runtime.h>
#include <math.h>

// Problem constants
#define BN_   2
#define SQ    2048
#define DM    1024
#define NHEAD 16
#define HD    64
#define NS    (BN_*SQ)        // 4096
#define QKVD  (3*DM)          // 3072

__device__ float g_qkv[(size_t)NS * QKVD];
__device__ float g_vals[(size_t)NS * DM];

__device__ __forceinline__ float cvt_tf32(float x) {
    unsigned u; asm("cvt.rna.tf32.f32 %0, %1;" : "=r"(u) : "f"(x));
    return __uint_as_float(u);
}
__device__ __forceinline__ float4 cvt4(float4 v) {
    return make_float4(cvt_tf32(v.x), cvt_tf32(v.y), cvt_tf32(v.z), cvt_tf32(v.w));
}
__device__ __forceinline__ void mma8(float4& d, float4 a, float b0, float b1) {
    asm("mma.sync.aligned.m16n8k8.row.col.f32.tf32.tf32.f32 "
        "{%0,%1,%2,%3},{%4,%5,%6,%7},{%8,%9},{%0,%1,%2,%3};"
        : "+f"(d.x), "+f"(d.y), "+f"(d.z), "+f"(d.w)
        : "r"(__float_as_uint(a.x)), "r"(__float_as_uint(a.y)),
          "r"(__float_as_uint(a.z)), "r"(__float_as_uint(a.w)),
          "r"(__float_as_uint(b0)),  "r"(__float_as_uint(b1)));
}

// Quad-pack stores (frag = contiguous 16B in smem)
__device__ __forceinline__ void stA_quad(float* buf, int row, int cst, int chalf, float4 v) {
    int gg = row & 7, R = row >> 4;
    int e  = ((row >> 3) & 1) + 2 * chalf;
    float* qb = buf + ((((R * 4 + cst) * 8 + gg) << 4) + e);
    int cx = cst & 3;
    qb[(0 ^ cx) << 2] = cvt_tf32(v.x);
    qb[(1 ^ cx) << 2] = cvt_tf32(v.y);
    qb[(2 ^ cx) << 2] = cvt_tf32(v.z);
    qb[(3 ^ cx) << 2] = cvt_tf32(v.w);
}
__device__ __forceinline__ void stB_quad(float* buf, int n, int cst, int chalf, float4 v) {
    int gg = n & 7, Ng = n >> 5, jj = (n >> 3) & 1;
    int e  = 2 * ((n >> 4) & 1) + chalf;
    float* qb = buf + (((((Ng * 2 + jj) * 4 + cst) * 8 + gg) << 4) + e);
    int cx = cst & 3;
    qb[(0 ^ cx) << 2] = cvt_tf32(v.x);
    qb[(1 ^ cx) << 2] = cvt_tf32(v.y);
    qb[(2 ^ cx) << 2] = cvt_tf32(v.z);
    qb[(3 ^ cx) << 2] = cvt_tf32(v.w);
}

// ---------------------------------------------------------------------------
// GEMM: C[M,N] = A[M,K]*B[N,K]^T. CTA tile 128x256, BK=32, 8 warps (64x64 each),
// double-buffered, register prefetch. Stage = A 4096 + B 8192 floats.
// ---------------------------------------------------------------------------
#define STG_FLOATS 12288
#define GEMM_SMEM (2 * STG_FLOATS * (int)sizeof(float))   // 98304

__global__ void __launch_bounds__(256, 1) gemm_mma(const float* __restrict__ A,
                                                   const float* __restrict__ B,
                                                   float* __restrict__ C,
                                                   int M, int N, int K) {
    extern __shared__ float gsm[];

    const int tid  = threadIdx.x;
    const int lane = tid & 31;
    const int warp = tid >> 5;
    const int g    = lane >> 2;
    const int q    = lane & 3;
    const int wm   = warp >> 2;       // 0..1 (64-row slab)
    const int wn   = warp & 3;        // 0..3 (64-col slab)
    const int m0   = blockIdx.y * 128;
    const int n0   = blockIdx.x * 256;

    const int lr    = tid >> 3;          // 0..31
    const int lk4   = (tid & 7) * 4;     // 0..28
    const int cst   = lk4 >> 3;
    const int chalf = (lk4 >> 2) & 1;

    float4 acc[4][8];
#pragma unroll
    for (int i = 0; i < 4; i++)
#pragma unroll
        for (int j = 0; j < 8; j++) acc[i][j] = make_float4(0.f, 0.f, 0.f, 0.f);

    float4 pa[4], pb[8];
    // prologue: tile 0
#pragma unroll
    for (int p = 0; p < 4; p++)
        pa[p] = *(const float4*)(A + (size_t)(m0 + lr + 32 * p) * K + lk4);
#pragma unroll
    for (int p = 0; p < 8; p++)
        pb[p] = *(const float4*)(B + (size_t)(n0 + lr + 32 * p) * K + lk4);
#pragma unroll
    for (int p = 0; p < 4; p++) stA_quad(gsm, lr + 32 * p, cst, chalf, pa[p]);
#pragma unroll
    for (int p = 0; p < 8; p++) stB_quad(gsm + 4096, lr + 32 * p, cst, chalf, pb[p]);
    __syncthreads();

    const int T = K >> 5;
    for (int t = 0; t < T; t++) {
        float* cb = gsm + (t & 1) * STG_FLOATS;

        if (t + 1 < T) {
            int k0 = (t + 1) << 5;
#pragma unroll
            for (int p = 0; p < 4; p++)
                pa[p] = *(const float4*)(A + (size_t)(m0 + lr + 32 * p) * K + k0 + lk4);
#pragma unroll
            for (int p = 0; p < 8; p++)
                pb[p] = *(const float4*)(B + (size_t)(n0 + lr + 32 * p) * K + k0 + lk4);
        }

#pragma unroll
        for (int c = 0; c < 4; c++) {
            float4 aq[4], bq[4];
#pragma unroll
            for (int i = 0; i < 4; i++)
                aq[i] = *(float4*)(cb + (((((wm * 4 + i) * 4 + c) * 8 + g) << 4) + ((q ^ c) << 2)));
#pragma unroll
            for (int jl = 0; jl < 4; jl++)
                bq[jl] = *(float4*)(cb + 4096 +
                    (((((wn * 2 + (jl >> 1)) * 2 + (jl & 1)) * 4 + c) * 8 + g) << 4) + ((q ^ c) << 2));
#pragma unroll
            for (int jl = 0; jl < 4; jl++) {
                int j1 = (jl >> 1) * 4 + (jl & 1);
#pragma unroll
                for (int i = 0; i < 4; i++) {
                    mma8(acc[i][j1],     aq[i], bq[jl].x, bq[jl].y);
                    mma8(acc[i][j1 + 2], aq[i], bq[jl].z, bq[jl].w);
                }
            }
        }

        if (t + 1 < T) {
            float* nb = gsm + ((t + 1) & 1) * STG_FLOATS;
#pragma unroll
            for (int p = 0; p < 4; p++) stA_quad(nb, lr + 32 * p, cst, chalf, pa[p]);
#pragma unroll
            for (int p = 0; p < 8; p++) stB_quad(nb + 4096, lr + 32 * p, cst, chalf, pb[p]);
        }
        __syncthreads();
    }

#pragma unroll
    for (int i = 0; i < 4; i++) {
#pragma unroll
        for (int j = 0; j < 8; j++) {
            int noff = ((j >> 2) * 32) + (((j >> 1) & 1) * 16) + ((j & 1) * 8);
            int row = m0 + wm * 64 + 16 * i + g;
            int col = n0 + wn * 64 + noff + 2 * q;
            *(float2*)&C[(size_t)row * N + col]       = make_float2(acc[i][j].x, acc[i][j].y);
            *(float2*)&C[(size_t)(row + 8) * N + col] = make_float2(acc[i][j].z, acc[i][j].w);
        }
    }
}

// ---------------------------------------------------------------------------
// Flash attention: 128 thr (4 warps), q-tile 128 (32 rows/warp), k-tile 64.
// K quad-packed; V [k][72] scalar (conflict-free); P quad-packed per warp.
// smem floats: KQ[0,4096) VS[4096,8704) PS[8704,16896)
// ---------------------------------------------------------------------------
#define ATTN_SMEM (16896 * (int)sizeof(float))

__global__ void __launch_bounds__(128) attn_mma(const float* __restrict__ qkv,
                                                float* __restrict__ vals) {
    extern __shared__ float sm[];
    float* KQ = sm;
    float* VS = sm + 4096;
    float* PS = sm + 8704;

    const int tid  = threadIdx.x;
    const int lane = tid & 31;
    const int warp = tid >> 5;
    const int g    = lane >> 2;
    const int q    = lane & 3;

    const int nh = blockIdx.y;
    const int n  = nh >> 4;
    const int h  = nh & 15;
    const int q0 = blockIdx.x * 128;

    const float* base = qkv + (size_t)n * SQ * QKVD + h * (3 * HD);

    // ---- stage Q (scaled) into PS as plain [r][64], lift fragments
#pragma unroll
    for (int p = 0; p < 16; p++) {
        int idx = tid + 128 * p;
        int r = idx >> 4, d4 = (idx & 15) * 4;
        float4 v = *(const float4*)(base + (size_t)(q0 + r) * QKVD + d4);
        v.x *= 0.125f; v.y *= 0.125f; v.z *= 0.125f; v.w *= 0.125f;
        *(float4*)&PS[r * 64 + d4] = cvt4(v);
    }
    __syncthreads();

    float4 qf[2][8];
#pragma unroll
    for (int m = 0; m < 2; m++) {
        int r = warp * 32 + 16 * m + g;
#pragma unroll
        for (int c = 0; c < 8; c++)
            qf[m][c] = make_float4(PS[r * 64 + 8 * c + q],
                                   PS[(r + 8) * 64 + 8 * c + q],
                                   PS[r * 64 + 8 * c + 4 + q],
                                   PS[(r + 8) * 64 + 8 * c + 4 + q]);
    }

    float mr[2][2], lr_[2][2];
#pragma unroll
    for (int m = 0; m < 2; m++) { mr[m][0] = mr[m][1] = -INFINITY; lr_[m][0] = lr_[m][1] = 0.f; }
    float4 oacc[2][8];
#pragma unroll
    for (int m = 0; m < 2; m++)
#pragma unroll
        for (int t = 0; t < 8; t++) oacc[m][t] = make_float4(0.f, 0.f, 0.f, 0.f);

    const int lrow  = tid >> 3;          // 0..15
    const int lk4   = (tid & 7) * 4;
    const int chalf = (lk4 >> 2) & 1;

    for (int kb = 0; kb < SQ / 64; kb++) {
        __syncthreads();
        const float* kvb = base + (size_t)(kb * 64) * QKVD;

        // K -> quad-packed KQ (64 rows x 64 cols)
#pragma unroll
        for (int p = 0; p < 4; p++) {
#pragma unroll
            for (int kh = 0; kh < 2; kh++) {
                int nl  = lrow + 16 * p;
                int col = kh * 32 + lk4;
                float4 v = *(const float4*)(kvb + (size_t)nl * QKVD + HD + col);
                int cs = col >> 3, cx = cs & 3;
                int gg = nl & 7, Ng = nl >> 5, jj = (nl >> 3) & 1;
                int e  = 2 * ((nl >> 4) & 1) + chalf;
                float* qb = KQ + (((((Ng * 2 + jj) * 8 + cs) * 8 + gg) << 4) + e);
                qb[(0 ^ cx) << 2] = cvt_tf32(v.x);
                qb[(1 ^ cx) << 2] = cvt_tf32(v.y);
                qb[(2 ^ cx) << 2] = cvt_tf32(v.z);
                qb[(3 ^ cx) << 2] = cvt_tf32(v.w);
            }
        }
        // V -> VS [k][72]
#pragma unroll
        for (int p = 0; p < 8; p++) {
            int idx = tid + 128 * p;
            int r = idx >> 4, d4 = (idx & 15) * 4;
            *(float4*)&VS[r * 72 + d4] =
                cvt4(*(const float4*)(kvb + (size_t)r * QKVD + 2 * HD + d4));
        }
        __syncthreads();

        // ---- S = Q K^T  (32 rows x 64 cols per warp)
        float4 sc[2][8];
#pragma unroll
        for (int m = 0; m < 2; m++)
#pragma unroll
            for (int j = 0; j < 8; j++) sc[m][j] = make_float4(0.f, 0.f, 0.f, 0.f);
#pragma unroll
        for (int c = 0; c < 8; c++) {
#pragma unroll
            for (int Ng = 0; Ng < 2; Ng++) {
#pragma unroll
                for (int jj = 0; jj < 2; jj++) {
                    float4 b = *(float4*)(KQ + (((((Ng * 2 + jj) * 8 + c) * 8 + g) << 4)
                                                + ((q ^ (c & 3)) << 2)));
                    int jlo = 4 * Ng + jj;
#pragma unroll
                    for (int m = 0; m < 2; m++) {
                        mma8(sc[m][jlo],     qf[m][c], b.x, b.y);
                        mma8(sc[m][jlo + 2], qf[m][c], b.z, b.w);
                    }
                }
            }
        }

        // ---- online softmax + P store (per m-tile)
        const int kq0 = 2 * (q & 1), ch = q >> 1;
#pragma unroll
        for (int m = 0; m < 2; m++) {
            float mx0 = -INFINITY, mx1 = -INFINITY;
#pragma unroll
            for (int j = 0; j < 8; j++) {
                mx0 = fmaxf(mx0, fmaxf(sc[m][j].x, sc[m][j].y));
                mx1 = fmaxf(mx1, fmaxf(sc[m][j].z, sc[m][j].w));
            }
#pragma unroll
            for (int off = 1; off <= 2; off <<= 1) {
                mx0 = fmaxf(mx0, __shfl_xor_sync(0xffffffffu, mx0, off));
                mx1 = fmaxf(mx1, __shfl_xor_sync(0xffffffffu, mx1, off));
            }
            float mn0 = fmaxf(mr[m][0], mx0), mn1 = fmaxf(mr[m][1], mx1);
            float corr0 = __expf(mr[m][0] - mn0), corr1 = __expf(mr[m][1] - mn1);

            float rs0 = 0.f, rs1 = 0.f;
#pragma unroll
            for (int j = 0; j < 8; j++) {
                float p0 = __expf(sc[m][j].x - mn0);
                float p1 = __expf(sc[m][j].y - mn0);
                float p2 = __expf(sc[m][j].z - mn1);
                float p3 = __expf(sc[m][j].w - mn1);
                rs0 += p0 + p1; rs1 += p2 + p3;
                float* bj = PS + ((((warp * 2 + m) * 8 + j) * 8 + g) << 4);
                *(float2*)&bj[(kq0 << 2)       + 2 * ch] = make_float2(cvt_tf32(p0), cvt_tf32(p2));
                *(float2*)&bj[((kq0 + 1) << 2) + 2 * ch] = make_float2(cvt_tf32(p1), cvt_tf32(p3));
            }
#pragma unroll
            for (int off = 1; off <= 2; off <<= 1) {
                rs0 += __shfl_xor_sync(0xffffffffu, rs0, off);
                rs1 += __shfl_xor_sync(0xffffffffu, rs1, off);
            }
            lr_[m][0] = lr_[m][0] * corr0 + rs0;  mr[m][0] = mn0;
            lr_[m][1] = lr_[m][1] * corr1 + rs1;  mr[m][1] = mn1;
#pragma unroll
            for (int t = 0; t < 8; t++) {
                oacc[m][t].x *= corr0; oacc[m][t].y *= corr0;
                oacc[m][t].z *= corr1; oacc[m][t].w *= corr1;
            }
        }
        __syncwarp();   // warp-private P strip visible

        // ---- O += P V  (V b-loads shared across both m-tiles)
#pragma unroll
        for (int c = 0; c < 8; c++) {
            float4 aq0 = *(float4*)(PS + (((((warp * 2 + 0) * 8 + c) * 8 + g) << 4) + (q << 2)));
            float4 aq1 = *(float4*)(PS + (((((warp * 2 + 1) * 8 + c) * 8 + g) << 4) + (q << 2)));
#pragma unroll
            for (int t = 0; t < 8; t++) {
                float b0 = VS[(8 * c + q) * 72 + 8 * t + g];
                float b1 = VS[(8 * c + 4 + q) * 72 + 8 * t + g];
                mma8(oacc[0][t], aq0, b0, b1);
                mma8(oacc[1][t], aq1, b0, b1);
            }
        }
    }

    // ---- normalize + write
    float* obase = vals + (size_t)(n * SQ + q0) * DM + h * HD;
#pragma unroll
    for (int m = 0; m < 2; m++) {
        int r = warp * 32 + 16 * m + g;
        float inv0 = 1.0f / lr_[m][0], inv1 = 1.0f / lr_[m][1];
#pragma unroll
        for (int t = 0; t < 8; t++) {
            int col = 8 * t + 2 * q;
            *(float2*)&obase[(size_t)r * DM + col] =
                make_float2(oacc[m][t].x * inv0, oacc[m][t].y * inv0);
            *(float2*)&obase[(size_t)(r + 8) * DM + col] =
                make_float2(oacc[m][t].z * inv1, oacc[m][t].w * inv1);
        }
    }
}

// ---------------------------------------------------------------------------
extern "C" void kernel_launch(void* const* d_in, const int* in_sizes, int n_in,
                              void* d_out, int out_size) {
    const float* x     = (const float*)d_in[0];
    const float* qkv_w = (const float*)d_in[1];
    const float* o_w   = (const float*)d_in[2];
    float* out = (float*)d_out;

    float *qkv_p = nullptr, *vals_p = nullptr;
    cudaGetSymbolAddress((void**)&qkv_p,  g_qkv);
    cudaGetSymbolAddress((void**)&vals_p, g_vals);

    cudaFuncSetAttribute(gemm_mma, cudaFuncAttributeMaxDynamicSharedMemorySize, GEMM_SMEM);
    cudaFuncSetAttribute(attn_mma, cudaFuncAttributeMaxDynamicSharedMemorySize, ATTN_SMEM);

    // 1) QKV projection: [4096,3072] = x @ qkv_w^T
    gemm_mma<<<dim3(QKVD / 256, NS / 128), 256, GEMM_SMEM>>>(x, qkv_w, qkv_p, NS, QKVD, DM);
    // 2) Attention: q-tile 128
    attn_mma<<<dim3(SQ / 128, BN_ * NHEAD), 128, ATTN_SMEM>>>(qkv_p, vals_p);
    // 3) Output projection
    gemm_mma<<<dim3(DM / 256, NS / 128), 256, GEMM_SMEM>>>(vals_p, o_w, out, NS, DM, DM);
}

// round 8
// speedup vs baseline: 5.3586x; 1.3599x over previous
#include <cuda_runtime.h>
#include <cuda_fp16.h>
#include <math.h>
#include <stdint.h>

// Problem constants
#define BN_   2
#define SQ    2048
#define DM    1024
#define NHEAD 16
#define HD    64
#define NS    (BN_*SQ)        // 4096
#define QKVD  (3*DM)          // 3072

__device__ float g_qkv[(size_t)NS * QKVD];
__device__ float g_vals[(size_t)NS * DM];

// ---------------------------------------------------------------------------
// helpers
// ---------------------------------------------------------------------------
__device__ __forceinline__ uint32_t smem_u32(const void* p) {
    uint32_t a;
    asm("{ .reg .u64 t; cvta.to.shared.u64 t, %1; cvt.u32.u64 %0, t; }" : "=r"(a) : "l"(p));
    return a;
}
__device__ __forceinline__ uint32_t pack2(float lo, float hi) {
    __half2 h = __floats2half2_rn(lo, hi);
    return *(uint32_t*)&h;
}
__device__ __forceinline__ uint2 pack4(float4 v) {
    return make_uint2(pack2(v.x, v.y), pack2(v.z, v.w));
}
__device__ __forceinline__ void ldsm4(uint32_t addr, uint32_t& r0, uint32_t& r1,
                                      uint32_t& r2, uint32_t& r3) {
    asm volatile("ldmatrix.sync.aligned.m8n8.x4.shared.b16 {%0,%1,%2,%3}, [%4];"
                 : "=r"(r0), "=r"(r1), "=r"(r2), "=r"(r3) : "r"(addr));
}
__device__ __forceinline__ void ldsm4t(uint32_t addr, uint32_t& r0, uint32_t& r1,
                                       uint32_t& r2, uint32_t& r3) {
    asm volatile("ldmatrix.sync.aligned.m8n8.x4.trans.shared.b16 {%0,%1,%2,%3}, [%4];"
                 : "=r"(r0), "=r"(r1), "=r"(r2), "=r"(r3) : "r"(addr));
}
__device__ __forceinline__ void mma16(float4& d, uint32_t a0, uint32_t a1, uint32_t a2,
                                      uint32_t a3, uint32_t b0, uint32_t b1) {
    asm("mma.sync.aligned.m16n8k16.row.col.f32.f16.f16.f32 "
        "{%0,%1,%2,%3},{%4,%5,%6,%7},{%8,%9},{%0,%1,%2,%3};"
        : "+f"(d.x), "+f"(d.y), "+f"(d.z), "+f"(d.w)
        : "r"(a0), "r"(a1), "r"(a2), "r"(a3), "r"(b0), "r"(b1));
}

// ---------------------------------------------------------------------------
// GEMM: C[M,N] = A[M,K]*B[N,K]^T, fp16 mma m16n8k16 + ldmatrix.
// CTA 128x256, BK=32, 8 warps (64x64), double-buffered, packed prefetch.
// smem: plain fp16 rows, stride 40 halfs (conflict-free ldmatrix: 20w mod 32).
// ---------------------------------------------------------------------------
#define ARS 40
#define A_HALFS (128 * ARS)               // 5120
#define B_HALFS (256 * ARS)               // 10240
#define STG_HALFS (A_HALFS + B_HALFS)     // 15360
#define GEMM_SMEM (2 * STG_HALFS * 2)     // 61440 B

__global__ void __launch_bounds__(256, 1) gemm_h(const float* __restrict__ A,
                                                 const float* __restrict__ B,
                                                 float* __restrict__ C,
                                                 int M, int N, int K) {
    extern __shared__ __half gsm[];

    const int tid  = threadIdx.x;
    const int lane = tid & 31;
    const int warp = tid >> 5;
    const int g    = lane >> 2;
    const int q    = lane & 3;
    const int wm   = warp >> 2;
    const int wn   = warp & 3;
    const int m0   = blockIdx.y * 128;
    const int n0   = blockIdx.x * 256;

    const int lr = tid >> 3;        // 0..31
    const int u  = tid & 7;         // k float4 index

    const int l7  = lane & 7;
    const int lb3 = (lane >> 3) & 1;
    const int lb4 = (lane >> 4) & 1;

    const uint32_t sb = smem_u32(gsm);
    const uint32_t aoff = ((wm * 64 + l7 + 8 * lb3) * ARS + 8 * lb4) * 2;
    const uint32_t boff = ((wn * 64 + l7 + 8 * lb3) * ARS + 8 * lb4) * 2 + A_HALFS * 2;

    float4 acc[4][8];
#pragma unroll
    for (int i = 0; i < 4; i++)
#pragma unroll
        for (int j = 0; j < 8; j++) acc[i][j] = make_float4(0.f, 0.f, 0.f, 0.f);

    uint2 pa[4], pb[8];
    // prologue
#pragma unroll
    for (int p = 0; p < 4; p++)
        pa[p] = pack4(*(const float4*)(A + (size_t)(m0 + lr + 32 * p) * K + 4 * u));
#pragma unroll
    for (int p = 0; p < 8; p++)
        pb[p] = pack4(*(const float4*)(B + (size_t)(n0 + lr + 32 * p) * K + 4 * u));
#pragma unroll
    for (int p = 0; p < 4; p++)
        *(uint2*)(gsm + (lr + 32 * p) * ARS + 4 * u) = pa[p];
#pragma unroll
    for (int p = 0; p < 8; p++)
        *(uint2*)(gsm + A_HALFS + (lr + 32 * p) * ARS + 4 * u) = pb[p];
    __syncthreads();

    const int T = K >> 5;
    for (int t = 0; t < T; t++) {
        const uint32_t cbase = sb + (t & 1) * (STG_HALFS * 2);

        if (t + 1 < T) {
            int k0 = (t + 1) << 5;
#pragma unroll
            for (int p = 0; p < 4; p++)
                pa[p] = pack4(*(const float4*)(A + (size_t)(m0 + lr + 32 * p) * K + k0 + 4 * u));
#pragma unroll
            for (int p = 0; p < 8; p++)
                pb[p] = pack4(*(const float4*)(B + (size_t)(n0 + lr + 32 * p) * K + k0 + 4 * u));
        }

#pragma unroll
        for (int c = 0; c < 2; c++) {
            uint32_t aq[4][4], bq[4][4];
#pragma unroll
            for (int i = 0; i < 4; i++)
                ldsm4(cbase + aoff + i * (16 * ARS * 2) + c * 32,
                      aq[i][0], aq[i][1], aq[i][2], aq[i][3]);
#pragma unroll
            for (int tt = 0; tt < 4; tt++)
                ldsm4(cbase + boff + tt * (16 * ARS * 2) + c * 32,
                      bq[tt][0], bq[tt][1], bq[tt][2], bq[tt][3]);
#pragma unroll
            for (int tt = 0; tt < 4; tt++)
#pragma unroll
                for (int i = 0; i < 4; i++) {
                    mma16(acc[i][2 * tt],     aq[i][0], aq[i][1], aq[i][2], aq[i][3],
                          bq[tt][0], bq[tt][2]);
                    mma16(acc[i][2 * tt + 1], aq[i][0], aq[i][1], aq[i][2], aq[i][3],
                          bq[tt][1], bq[tt][3]);
                }
        }

        if (t + 1 < T) {
            __half* nb = gsm + ((t + 1) & 1) * STG_HALFS;
#pragma unroll
            for (int p = 0; p < 4; p++)
                *(uint2*)(nb + (lr + 32 * p) * ARS + 4 * u) = pa[p];
#pragma unroll
            for (int p = 0; p < 8; p++)
                *(uint2*)(nb + A_HALFS + (lr + 32 * p) * ARS + 4 * u) = pb[p];
        }
        __syncthreads();
    }

#pragma unroll
    for (int i = 0; i < 4; i++) {
#pragma unroll
        for (int j = 0; j < 8; j++) {
            int row = m0 + wm * 64 + 16 * i + g;
            int col = n0 + wn * 64 + 8 * j + 2 * q;
            *(float2*)&C[(size_t)row * N + col]       = make_float2(acc[i][j].x, acc[i][j].y);
            *(float2*)&C[(size_t)(row + 8) * N + col] = make_float2(acc[i][j].z, acc[i][j].w);
        }
    }
}

// ---------------------------------------------------------------------------
// Flash attention (fp16 mma + ldmatrix). 4 warps, q-tile 128 (32 rows/warp),
// k-tile 64. Q frags in regs; K plain [n][72]; V plain [k][72] read via
// ldmatrix.trans; P stays in registers (acc layout == A-frag layout).
// ---------------------------------------------------------------------------
#define KRS 72
#define ATTN_SMEM (128 * KRS * 2)   // 18432 B  (Q stage overlays K+V)

__global__ void __launch_bounds__(128) attn_h(const float* __restrict__ qkv,
                                              float* __restrict__ vals) {
    extern __shared__ __half sm[];
    __half* VS = sm + 64 * KRS;

    const int tid  = threadIdx.x;
    const int lane = tid & 31;
    const int warp = tid >> 5;
    const int g    = lane >> 2;
    const int q    = lane & 3;
    const int l7   = lane & 7;
    const int lb3  = (lane >> 3) & 1;
    const int lb4  = (lane >> 4) & 1;

    const int nh = blockIdx.y;
    const int n  = nh >> 4;
    const int h  = nh & 15;
    const int q0 = blockIdx.x * 128;

    const float* base = qkv + (size_t)n * SQ * QKVD + h * (3 * HD);
    const uint32_t sb = smem_u32(sm);

    // ---- stage Q (scaled), lift fragments via ldmatrix
#pragma unroll
    for (int p = 0; p < 16; p++) {
        int idx = tid + 128 * p;
        int r = idx >> 4, u = idx & 15;
        float4 v = *(const float4*)(base + (size_t)(q0 + r) * QKVD + 4 * u);
        v.x *= 0.125f; v.y *= 0.125f; v.z *= 0.125f; v.w *= 0.125f;
        *(uint2*)(sm + r * KRS + 4 * u) = pack4(v);
    }
    __syncthreads();

    uint32_t qf[2][4][4];
    {
        uint32_t qbase = sb + ((warp * 32 + l7 + 8 * lb3) * KRS + 8 * lb4) * 2;
#pragma unroll
        for (int m = 0; m < 2; m++)
#pragma unroll
            for (int c = 0; c < 4; c++)
                ldsm4(qbase + m * (16 * KRS * 2) + c * 32,
                      qf[m][c][0], qf[m][c][1], qf[m][c][2], qf[m][c][3]);
    }

    const uint32_t kbase = sb + ((l7 + 8 * lb3) * KRS + 8 * lb4) * 2;
    const uint32_t vbase = sb + 64 * KRS * 2 + ((l7 + 8 * lb4) * KRS + 8 * lb3) * 2;

    float mr[2][2], lsum[2][2];
#pragma unroll
    for (int m = 0; m < 2; m++) { mr[m][0] = mr[m][1] = -INFINITY; lsum[m][0] = lsum[m][1] = 0.f; }
    float4 oacc[2][8];
#pragma unroll
    for (int m = 0; m < 2; m++)
#pragma unroll
        for (int j = 0; j < 8; j++) oacc[m][j] = make_float4(0.f, 0.f, 0.f, 0.f);

    for (int kb = 0; kb < SQ / 64; kb++) {
        __syncthreads();   // smem reuse (incl. first-iter Q overwrite)
        const float* kvb = base + (size_t)(kb * 64) * QKVD;
#pragma unroll
        for (int p = 0; p < 8; p++) {
            int idx = tid + 128 * p;
            int r = idx >> 4, u = idx & 15;
            const float* rp = kvb + (size_t)r * QKVD;
            *(uint2*)(sm + r * KRS + 4 * u) = pack4(*(const float4*)(rp + HD + 4 * u));
            *(uint2*)(VS + r * KRS + 4 * u) = pack4(*(const float4*)(rp + 2 * HD + 4 * u));
        }
        __syncthreads();

        // ---- S = Q K^T
        float4 sc[2][8];
#pragma unroll
        for (int m = 0; m < 2; m++)
#pragma unroll
            for (int j = 0; j < 8; j++) sc[m][j] = make_float4(0.f, 0.f, 0.f, 0.f);
#pragma unroll
        for (int c = 0; c < 4; c++)
#pragma unroll
            for (int tt = 0; tt < 4; tt++) {
                uint32_t b0, b1, b2, b3;
                ldsm4(kbase + tt * (16 * KRS * 2) + c * 32, b0, b1, b2, b3);
#pragma unroll
                for (int m = 0; m < 2; m++) {
                    mma16(sc[m][2 * tt],     qf[m][c][0], qf[m][c][1], qf[m][c][2], qf[m][c][3], b0, b2);
                    mma16(sc[m][2 * tt + 1], qf[m][c][0], qf[m][c][1], qf[m][c][2], qf[m][c][3], b1, b3);
                }
            }

        // ---- online softmax; P packed straight into A-fragments
        uint32_t pf[2][4][4];
#pragma unroll
        for (int m = 0; m < 2; m++) {
            float mx0 = -INFINITY, mx1 = -INFINITY;
#pragma unroll
            for (int j = 0; j < 8; j++) {
                mx0 = fmaxf(mx0, fmaxf(sc[m][j].x, sc[m][j].y));
                mx1 = fmaxf(mx1, fmaxf(sc[m][j].z, sc[m][j].w));
            }
#pragma unroll
            for (int off = 1; off <= 2; off <<= 1) {
                mx0 = fmaxf(mx0, __shfl_xor_sync(0xffffffffu, mx0, off));
                mx1 = fmaxf(mx1, __shfl_xor_sync(0xffffffffu, mx1, off));
            }
            float mn0 = fmaxf(mr[m][0], mx0), mn1 = fmaxf(mr[m][1], mx1);
            float corr0 = __expf(mr[m][0] - mn0), corr1 = __expf(mr[m][1] - mn1);

            float rs0 = 0.f, rs1 = 0.f;
#pragma unroll
            for (int j = 0; j < 8; j++) {
                float p0 = __expf(sc[m][j].x - mn0);
                float p1 = __expf(sc[m][j].y - mn0);
                float p2 = __expf(sc[m][j].z - mn1);
                float p3 = __expf(sc[m][j].w - mn1);
                rs0 += p0 + p1; rs1 += p2 + p3;
                int c = j >> 1;
                if ((j & 1) == 0) { pf[m][c][0] = pack2(p0, p1); pf[m][c][1] = pack2(p2, p3); }
                else              { pf[m][c][2] = pack2(p0, p1); pf[m][c][3] = pack2(p2, p3); }
            }
#pragma unroll
            for (int off = 1; off <= 2; off <<= 1) {
                rs0 += __shfl_xor_sync(0xffffffffu, rs0, off);
                rs1 += __shfl_xor_sync(0xffffffffu, rs1, off);
            }
            lsum[m][0] = lsum[m][0] * corr0 + rs0;  mr[m][0] = mn0;
            lsum[m][1] = lsum[m][1] * corr1 + rs1;  mr[m][1] = mn1;
#pragma unroll
            for (int j = 0; j < 8; j++) {
                oacc[m][j].x *= corr0; oacc[m][j].y *= corr0;
                oacc[m][j].z *= corr1; oacc[m][j].w *= corr1;
            }
        }

        // ---- O += P V   (V fragments via ldmatrix.trans; no smem for P)
#pragma unroll
        for (int c = 0; c < 4; c++)
#pragma unroll
            for (int td = 0; td < 4; td++) {
                uint32_t v0, v1, v2, v3;
                ldsm4t(vbase + c * (16 * KRS * 2) + td * 32, v0, v1, v2, v3);
#pragma unroll
                for (int m = 0; m < 2; m++) {
                    mma16(oacc[m][2 * td],     pf[m][c][0], pf[m][c][1], pf[m][c][2], pf[m][c][3], v0, v2);
                    mma16(oacc[m][2 * td + 1], pf[m][c][0], pf[m][c][1], pf[m][c][2], pf[m][c][3], v1, v3);
                }
            }
    }

    // ---- normalize + write
    float* obase = vals + (size_t)(n * SQ + q0) * DM + h * HD;
#pragma unroll
    for (int m = 0; m < 2; m++) {
        int r = warp * 32 + 16 * m + g;
        float inv0 = 1.0f / lsum[m][0], inv1 = 1.0f / lsum[m][1];
#pragma unroll
        for (int j = 0; j < 8; j++) {
            int col = 8 * j + 2 * q;
            *(float2*)&obase[(size_t)r * DM + col] =
                make_float2(oacc[m][j].x * inv0, oacc[m][j].y * inv0);
            *(float2*)&obase[(size_t)(r + 8) * DM + col] =
                make_float2(oacc[m][j].z * inv1, oacc[m][j].w * inv1);
        }
    }
}

// ---------------------------------------------------------------------------
extern "C" void kernel_launch(void* const* d_in, const int* in_sizes, int n_in,
                              void* d_out, int out_size) {
    const float* x     = (const float*)d_in[0];
    const float* qkv_w = (const float*)d_in[1];
    const float* o_w   = (const float*)d_in[2];
    float* out = (float*)d_out;

    float *qkv_p = nullptr, *vals_p = nullptr;
    cudaGetSymbolAddress((void**)&qkv_p,  g_qkv);
    cudaGetSymbolAddress((void**)&vals_p, g_vals);

    cudaFuncSetAttribute(gemm_h, cudaFuncAttributeMaxDynamicSharedMemorySize, GEMM_SMEM);
    cudaFuncSetAttribute(attn_h, cudaFuncAttributeMaxDynamicSharedMemorySize, ATTN_SMEM);

    // 1) QKV projection
    gemm_h<<<dim3(QKVD / 256, NS / 128), 256, GEMM_SMEM>>>(x, qkv_w, qkv_p, NS, QKVD, DM);
    // 2) Attention
    attn_h<<<dim3(SQ / 128, BN_ * NHEAD), 128, ATTN_SMEM>>>(qkv_p, vals_p);
    // 3) Output projection
    gemm_h<<<dim3(DM / 256, NS / 128), 256, GEMM_SMEM>>>(vals_p, o_w, out, NS, DM, DM);
}

// round 9
// speedup vs baseline: 6.6823x; 1.2470x over previous
#include <cuda_runtime.h>
#include <cuda_fp16.h>
#include <math.h>
#include <stdint.h>

// Problem constants
#define BN_   2
#define SQ    2048
#define DM    1024
#define NHEAD 16
#define HD    64
#define NS    (BN_*SQ)        // 4096
#define QKVD  (3*DM)          // 3072

// fp16 device-global scratch
__device__ __half g_xh[(size_t)NS * DM];      // x in fp16
__device__ __half g_wqkv[(size_t)QKVD * DM];  // qkv_w in fp16
__device__ __half g_wo[(size_t)DM * DM];      // o_w in fp16
__device__ __half g_qkvh[(size_t)NS * QKVD];  // qkv activations fp16
__device__ __half g_valsh[(size_t)NS * DM];   // attention output fp16

// ---------------------------------------------------------------------------
// helpers
// ---------------------------------------------------------------------------
__device__ __forceinline__ uint32_t smem_u32(const void* p) {
    uint32_t a;
    asm("{ .reg .u64 t; cvta.to.shared.u64 t, %1; cvt.u32.u64 %0, t; }" : "=r"(a) : "l"(p));
    return a;
}
__device__ __forceinline__ uint32_t pack2(float lo, float hi) {
    __half2 h = __floats2half2_rn(lo, hi);
    return *(uint32_t*)&h;
}
__device__ __forceinline__ uint2 pack4(float4 v) {
    return make_uint2(pack2(v.x, v.y), pack2(v.z, v.w));
}
__device__ __forceinline__ void cp16(uint32_t dst, const void* src) {
    asm volatile("cp.async.cg.shared.global [%0], [%1], 16;" :: "r"(dst), "l"(src));
}
#define CP_COMMIT() asm volatile("cp.async.commit_group;" ::: "memory")
#define CP_WAIT(n)  asm volatile("cp.async.wait_group %0;" :: "n"(n) : "memory")

__device__ __forceinline__ void ldsm4(uint32_t addr, uint32_t& r0, uint32_t& r1,
                                      uint32_t& r2, uint32_t& r3) {
    asm volatile("ldmatrix.sync.aligned.m8n8.x4.shared.b16 {%0,%1,%2,%3}, [%4];"
                 : "=r"(r0), "=r"(r1), "=r"(r2), "=r"(r3) : "r"(addr));
}
__device__ __forceinline__ void ldsm4t(uint32_t addr, uint32_t& r0, uint32_t& r1,
                                       uint32_t& r2, uint32_t& r3) {
    asm volatile("ldmatrix.sync.aligned.m8n8.x4.trans.shared.b16 {%0,%1,%2,%3}, [%4];"
                 : "=r"(r0), "=r"(r1), "=r"(r2), "=r"(r3) : "r"(addr));
}
__device__ __forceinline__ void mma16(float4& d, uint32_t a0, uint32_t a1, uint32_t a2,
                                      uint32_t a3, uint32_t b0, uint32_t b1) {
    asm("mma.sync.aligned.m16n8k16.row.col.f32.f16.f16.f32 "
        "{%0,%1,%2,%3},{%4,%5,%6,%7},{%8,%9},{%0,%1,%2,%3};"
        : "+f"(d.x), "+f"(d.y), "+f"(d.z), "+f"(d.w)
        : "r"(a0), "r"(a1), "r"(a2), "r"(a3), "r"(b0), "r"(b1));
}

// ---------------------------------------------------------------------------
// fp32 -> fp16 conversion (vectorized)
// ---------------------------------------------------------------------------
__global__ void f2h(const float* __restrict__ src, __half* __restrict__ dst, int n4) {
    int i = blockIdx.x * blockDim.x + threadIdx.x;
    if (i < n4) ((uint2*)dst)[i] = pack4(((const float4*)src)[i]);
}

// ---------------------------------------------------------------------------
// GEMM: C[M,N] = A[M,K]*B[N,K]^T, fp16 in, fp16-or-fp32 out.
// CTA 128x256, BK=32, 8 warps (64x64), 3-stage cp.async pipeline.
// smem stride 40 halfs (conflict-free ldmatrix).
// ---------------------------------------------------------------------------
#define ARS 40
#define A_HALFS (128 * ARS)               // 5120
#define B_HALFS (256 * ARS)               // 10240
#define STG_HALFS (A_HALFS + B_HALFS)     // 15360
#define STG_BYTES (STG_HALFS * 2)         // 30720
#define GEMM_SMEM (3 * STG_BYTES)         // 92160

template <typename OUT>
__global__ void __launch_bounds__(256, 1) gemm_h(const __half* __restrict__ A,
                                                 const __half* __restrict__ B,
                                                 OUT* __restrict__ C,
                                                 int M, int N, int K) {
    extern __shared__ __half gsm[];

    const int tid  = threadIdx.x;
    const int lane = tid & 31;
    const int warp = tid >> 5;
    const int g    = lane >> 2;
    const int q    = lane & 3;
    const int wm   = warp >> 2;
    const int wn   = warp & 3;
    const int m0   = blockIdx.y * 128;
    const int n0   = blockIdx.x * 256;

    const int l7  = lane & 7;
    const int lb3 = (lane >> 3) & 1;
    const int lb4 = (lane >> 4) & 1;

    const uint32_t sb   = smem_u32(gsm);
    const uint32_t aoff = ((wm * 64 + l7 + 8 * lb3) * ARS + 8 * lb4) * 2;
    const uint32_t boff = ((wn * 64 + l7 + 8 * lb3) * ARS + 8 * lb4) * 2 + A_HALFS * 2;

    // cp.async chunk mapping (16B = 8 halfs)
    const int ar = tid >> 2, ach = tid & 3;     // A: 2 passes (rows 0..63, 64..127)
    const int br = tid >> 2, bch = tid & 3;     // B: 4 passes

    float4 acc[4][8];
#pragma unroll
    for (int i = 0; i < 4; i++)
#pragma unroll
        for (int j = 0; j < 8; j++) acc[i][j] = make_float4(0.f, 0.f, 0.f, 0.f);

    const int T = K >> 5;

    // stage issue
    auto issue = [&](int t, int buf) {
        const uint32_t db = sb + buf * STG_BYTES;
        const int k0 = t << 5;
#pragma unroll
        for (int p = 0; p < 2; p++) {
            int row = ar + 64 * p;
            cp16(db + (row * ARS + 8 * ach) * 2,
                 A + (size_t)(m0 + row) * K + k0 + 8 * ach);
        }
#pragma unroll
        for (int p = 0; p < 4; p++) {
            int row = br + 64 * p;
            cp16(db + A_HALFS * 2 + (row * ARS + 8 * bch) * 2,
                 B + (size_t)(n0 + row) * K + k0 + 8 * bch);
        }
        CP_COMMIT();
    };

    issue(0, 0);
    issue(1, 1);

    for (int t = 0; t < T; t++) {
        CP_WAIT(1);
        __syncthreads();
        if (t + 2 < T) issue(t + 2, (t + 2) % 3); else CP_COMMIT();

        const uint32_t cbase = sb + (t % 3) * STG_BYTES;
#pragma unroll
        for (int c = 0; c < 2; c++) {
            uint32_t aq[4][4], bq[4][4];
#pragma unroll
            for (int i = 0; i < 4; i++)
                ldsm4(cbase + aoff + i * (16 * ARS * 2) + c * 32,
                      aq[i][0], aq[i][1], aq[i][2], aq[i][3]);
#pragma unroll
            for (int tt = 0; tt < 4; tt++)
                ldsm4(cbase + boff + tt * (16 * ARS * 2) + c * 32,
                      bq[tt][0], bq[tt][1], bq[tt][2], bq[tt][3]);
#pragma unroll
            for (int tt = 0; tt < 4; tt++)
#pragma unroll
                for (int i = 0; i < 4; i++) {
                    mma16(acc[i][2 * tt],     aq[i][0], aq[i][1], aq[i][2], aq[i][3],
                          bq[tt][0], bq[tt][2]);
                    mma16(acc[i][2 * tt + 1], aq[i][0], aq[i][1], aq[i][2], aq[i][3],
                          bq[tt][1], bq[tt][3]);
                }
        }
    }

#pragma unroll
    for (int i = 0; i < 4; i++) {
#pragma unroll
        for (int j = 0; j < 8; j++) {
            int row = m0 + wm * 64 + 16 * i + g;
            int col = n0 + wn * 64 + 8 * j + 2 * q;
            if constexpr (sizeof(OUT) == 2) {
                *(uint32_t*)&C[(size_t)row * N + col]       = pack2(acc[i][j].x, acc[i][j].y);
                *(uint32_t*)&C[(size_t)(row + 8) * N + col] = pack2(acc[i][j].z, acc[i][j].w);
            } else {
                *(float2*)&C[(size_t)row * N + col]       = make_float2(acc[i][j].x, acc[i][j].y);
                *(float2*)&C[(size_t)(row + 8) * N + col] = make_float2(acc[i][j].z, acc[i][j].w);
            }
        }
    }
}

// ---------------------------------------------------------------------------
// Flash attention, fp16 in (g_qkvh) / fp16 out (g_valsh).
// 4 warps, q-tile 128 (32 rows/warp), k-tile 64, K/V double-buffered cp.async.
// Q frags in regs (scaled by 2^-3 post-ldsm); P in regs.
// Stage: K [0, 64*72), V [64*72, 2*64*72) halfs; 2 stages.
// ---------------------------------------------------------------------------
#define KRS 72
#define AT_STG_HALFS (2 * 64 * KRS)         // 9216
#define AT_STG_BYTES (AT_STG_HALFS * 2)     // 18432
#define ATTN_SMEM (2 * AT_STG_BYTES)        // 36864

__global__ void __launch_bounds__(128) attn_h(const __half* __restrict__ qkv,
                                              __half* __restrict__ vals) {
    extern __shared__ __half sm[];

    const int tid  = threadIdx.x;
    const int lane = tid & 31;
    const int warp = tid >> 5;
    const int g    = lane >> 2;
    const int q    = lane & 3;
    const int l7   = lane & 7;
    const int lb3  = (lane >> 3) & 1;
    const int lb4  = (lane >> 4) & 1;

    const int nh = blockIdx.y;
    const int n  = nh >> 4;
    const int h  = nh & 15;
    const int q0 = blockIdx.x * 128;

    const __half* base = qkv + (size_t)n * SQ * QKVD + h * (3 * HD);
    const uint32_t sb = smem_u32(sm);

    // ---- stage Q via cp.async into stage region (overlaps; used before loop)
    {
        const __half* qb = base + (size_t)q0 * QKVD;
#pragma unroll
        for (int p = 0; p < 8; p++) {
            int idx = tid + 128 * p;           // 0..1023
            int r = idx >> 3, ch = idx & 7;
            cp16(sb + (r * KRS + 8 * ch) * 2, qb + (size_t)r * QKVD + 8 * ch);
        }
        CP_COMMIT();
        CP_WAIT(0);
        __syncthreads();
    }

    uint32_t qf[2][4][4];
    {
        const uint32_t qbase = sb + ((warp * 32 + l7 + 8 * lb3) * KRS + 8 * lb4) * 2;
        const __half2 s2 = __float2half2_rn(0.125f);
#pragma unroll
        for (int m = 0; m < 2; m++)
#pragma unroll
            for (int c = 0; c < 4; c++) {
                ldsm4(qbase + m * (16 * KRS * 2) + c * 32,
                      qf[m][c][0], qf[m][c][1], qf[m][c][2], qf[m][c][3]);
#pragma unroll
                for (int k = 0; k < 4; k++) {
                    __half2 v = __hmul2(*(__half2*)&qf[m][c][k], s2);
                    qf[m][c][k] = *(uint32_t*)&v;
                }
            }
    }
    __syncthreads();   // Q reads done before K/V prologue overwrites

    const uint32_t koff = ((l7 + 8 * lb3) * KRS + 8 * lb4) * 2;
    const uint32_t voff = 64 * KRS * 2 + ((l7 + 8 * lb4) * KRS + 8 * lb3) * 2;

    // K/V stage issue
    auto issue_kv = [&](int kb, int buf) {
        const uint32_t db = sb + buf * AT_STG_BYTES;
        const __half* kvb = base + (size_t)(kb * 64) * QKVD;
#pragma unroll
        for (int p = 0; p < 4; p++) {
            int idx = tid + 128 * p;           // 0..511
            int r = idx >> 3, ch = idx & 7;
            const __half* rp = kvb + (size_t)r * QKVD;
            cp16(db + (r * KRS + 8 * ch) * 2,                 rp + HD + 8 * ch);
            cp16(db + (64 * KRS + r * KRS + 8 * ch) * 2,      rp + 2 * HD + 8 * ch);
        }
        CP_COMMIT();
    };

    float mr[2][2], lsum[2][2];
#pragma unroll
    for (int m = 0; m < 2; m++) { mr[m][0] = mr[m][1] = -INFINITY; lsum[m][0] = lsum[m][1] = 0.f; }
    float4 oacc[2][8];
#pragma unroll
    for (int m = 0; m < 2; m++)
#pragma unroll
        for (int j = 0; j < 8; j++) oacc[m][j] = make_float4(0.f, 0.f, 0.f, 0.f);

    issue_kv(0, 0);

    for (int kb = 0; kb < SQ / 64; kb++) {
        CP_WAIT(0);
        __syncthreads();
        if (kb + 1 < SQ / 64) issue_kv(kb + 1, (kb + 1) & 1);

        const uint32_t cbase = sb + (kb & 1) * AT_STG_BYTES;

        // ---- S = Q K^T
        float4 sc[2][8];
#pragma unroll
        for (int m = 0; m < 2; m++)
#pragma unroll
            for (int j = 0; j < 8; j++) sc[m][j] = make_float4(0.f, 0.f, 0.f, 0.f);
#pragma unroll
        for (int c = 0; c < 4; c++)
#pragma unroll
            for (int tt = 0; tt < 4; tt++) {
                uint32_t b0, b1, b2, b3;
                ldsm4(cbase + koff + tt * (16 * KRS * 2) + c * 32, b0, b1, b2, b3);
#pragma unroll
                for (int m = 0; m < 2; m++) {
                    mma16(sc[m][2 * tt],     qf[m][c][0], qf[m][c][1], qf[m][c][2], qf[m][c][3], b0, b2);
                    mma16(sc[m][2 * tt + 1], qf[m][c][0], qf[m][c][1], qf[m][c][2], qf[m][c][3], b1, b3);
                }
            }

        // ---- online softmax; P packed straight into A-fragments
        uint32_t pf[2][4][4];
#pragma unroll
        for (int m = 0; m < 2; m++) {
            float mx0 = -INFINITY, mx1 = -INFINITY;
#pragma unroll
            for (int j = 0; j < 8; j++) {
                mx0 = fmaxf(mx0, fmaxf(sc[m][j].x, sc[m][j].y));
                mx1 = fmaxf(mx1, fmaxf(sc[m][j].z, sc[m][j].w));
            }
#pragma unroll
            for (int off = 1; off <= 2; off <<= 1) {
                mx0 = fmaxf(mx0, __shfl_xor_sync(0xffffffffu, mx0, off));
                mx1 = fmaxf(mx1, __shfl_xor_sync(0xffffffffu, mx1, off));
            }
            float mn0 = fmaxf(mr[m][0], mx0), mn1 = fmaxf(mr[m][1], mx1);
            float corr0 = __expf(mr[m][0] - mn0), corr1 = __expf(mr[m][1] - mn1);

            float rs0 = 0.f, rs1 = 0.f;
#pragma unroll
            for (int j = 0; j < 8; j++) {
                float p0 = __expf(sc[m][j].x - mn0);
                float p1 = __expf(sc[m][j].y - mn0);
                float p2 = __expf(sc[m][j].z - mn1);
                float p3 = __expf(sc[m][j].w - mn1);
                rs0 += p0 + p1; rs1 += p2 + p3;
                int c = j >> 1;
                if ((j & 1) == 0) { pf[m][c][0] = pack2(p0, p1); pf[m][c][1] = pack2(p2, p3); }
                else              { pf[m][c][2] = pack2(p0, p1); pf[m][c][3] = pack2(p2, p3); }
            }
#pragma unroll
            for (int off = 1; off <= 2; off <<= 1) {
                rs0 += __shfl_xor_sync(0xffffffffu, rs0, off);
                rs1 += __shfl_xor_sync(0xffffffffu, rs1, off);
            }
            lsum[m][0] = lsum[m][0] * corr0 + rs0;  mr[m][0] = mn0;
            lsum[m][1] = lsum[m][1] * corr1 + rs1;  mr[m][1] = mn1;
#pragma unroll
            for (int j = 0; j < 8; j++) {
                oacc[m][j].x *= corr0; oacc[m][j].y *= corr0;
                oacc[m][j].z *= corr1; oacc[m][j].w *= corr1;
            }
        }

        // ---- O += P V  (ldmatrix.trans on V; P in regs)
#pragma unroll
        for (int c = 0; c < 4; c++)
#pragma unroll
            for (int td = 0; td < 4; td++) {
                uint32_t v0, v1, v2, v3;
                ldsm4t(cbase + voff + c * (16 * KRS * 2) + td * 32, v0, v1, v2, v3);
#pragma unroll
                for (int m = 0; m < 2; m++) {
                    mma16(oacc[m][2 * td],     pf[m][c][0], pf[m][c][1], pf[m][c][2], pf[m][c][3], v0, v2);
                    mma16(oacc[m][2 * td + 1], pf[m][c][0], pf[m][c][1], pf[m][c][2], pf[m][c][3], v1, v3);
                }
            }
    }

    // ---- normalize + write fp16
    __half* obase = vals + (size_t)(n * SQ + q0) * DM + h * HD;
#pragma unroll
    for (int m = 0; m < 2; m++) {
        int r = warp * 32 + 16 * m + g;
        float inv0 = 1.0f / lsum[m][0], inv1 = 1.0f / lsum[m][1];
#pragma unroll
        for (int j = 0; j < 8; j++) {
            int col = 8 * j + 2 * q;
            *(uint32_t*)&obase[(size_t)r * DM + col] =
                pack2(oacc[m][j].x * inv0, oacc[m][j].y * inv0);
            *(uint32_t*)&obase[(size_t)(r + 8) * DM + col] =
                pack2(oacc[m][j].z * inv1, oacc[m][j].w * inv1);
        }
    }
}

// ---------------------------------------------------------------------------
extern "C" void kernel_launch(void* const* d_in, const int* in_sizes, int n_in,
                              void* d_out, int out_size) {
    const float* x     = (const float*)d_in[0];
    const float* qkv_w = (const float*)d_in[1];
    const float* o_w   = (const float*)d_in[2];
    float* out = (float*)d_out;

    __half *xh, *wqkv, *wo, *qkvh, *valsh;
    cudaGetSymbolAddress((void**)&xh,    g_xh);
    cudaGetSymbolAddress((void**)&wqkv,  g_wqkv);
    cudaGetSymbolAddress((void**)&wo,    g_wo);
    cudaGetSymbolAddress((void**)&qkvh,  g_qkvh);
    cudaGetSymbolAddress((void**)&valsh, g_valsh);

    cudaFuncSetAttribute(gemm_h<__half>, cudaFuncAttributeMaxDynamicSharedMemorySize, GEMM_SMEM);
    cudaFuncSetAttribute(gemm_h<float>,  cudaFuncAttributeMaxDynamicSharedMemorySize, GEMM_SMEM);
    cudaFuncSetAttribute(attn_h,         cudaFuncAttributeMaxDynamicSharedMemorySize, ATTN_SMEM);

    // 0) fp32 -> fp16 conversions
    f2h<<<(NS * DM / 4 + 255) / 256, 256>>>(x, xh, NS * DM / 4);
    f2h<<<(QKVD * DM / 4 + 255) / 256, 256>>>(qkv_w, wqkv, QKVD * DM / 4);
    f2h<<<(DM * DM / 4 + 255) / 256, 256>>>(o_w, wo, DM * DM / 4);

    // 1) QKV projection (fp16 out)
    gemm_h<__half><<<dim3(QKVD / 256, NS / 128), 256, GEMM_SMEM>>>(xh, wqkv, qkvh, NS, QKVD, DM);
    // 2) Attention (fp16 in/out)
    attn_h<<<dim3(SQ / 128, BN_ * NHEAD), 128, ATTN_SMEM>>>(qkvh, valsh);
    // 3) Output projection (fp32 out)
    gemm_h<float><<<dim3(DM / 256, NS / 128), 256, GEMM_SMEM>>>(valsh, wo, out, NS, DM, DM);
}